// round 15
// baseline (speedup 1.0000x reference)
#include <cuda_runtime.h>
#include <cstddef>

#define B_   32
#define T_   2048
#define E_   128
#define G_   4              // CTAs per batch
#define ROWS 512            // T_ / G_  rows per CTA
#define NW   32             // warps per CTA
#define RPW  16             // rows per warp
#define INV_T (1.0f / 2048.0f)

// ---------------- scratch (device globals; zero-init; no allocation) -------
__device__ float  g_s_part[2][B_][G_][E_];   // per-CTA column-sum partials
__device__ float  g_c_part[2][B_][G_][E_];   // per-CTA c partials
__device__ float2 g_stats [2][B_][G_];       // per-CTA (local max, local sumexp)
__device__ float  g_o_part[2][B_][G_][E_];   // per-CTA weighted sums (local weights)
__device__ unsigned g_bar[B_][4];            // per-batch counters [A,B,D,reset]

static __device__ __forceinline__ float dot4(float4 a, float4 b) {
    return fmaf(a.x, b.x, fmaf(a.y, b.y, fmaf(a.z, b.z, a.w * b.w)));
}
static __device__ __forceinline__ float wmax(float v) {
    #pragma unroll
    for (int off = 16; off; off >>= 1) v = fmaxf(v, __shfl_xor_sync(0xffffffffu, v, off));
    return v;
}
static __device__ __forceinline__ float wsum(float v) {
    #pragma unroll
    for (int off = 16; off; off >>= 1) v += __shfl_xor_sync(0xffffffffu, v, off);
    return v;
}

// batch-scoped barrier: all G_ CTAs of this batch arrive, then proceed.
// All 128 CTAs are co-resident (grid 128 <= 148 SMs, 1 CTA/SM): spin is safe.
static __device__ __forceinline__ void batch_bar(unsigned* cnt) {
    __threadfence();
    __syncthreads();
    if (threadIdx.x == 0) {
        atomicAdd(cnt, 1u);
        while (*(volatile unsigned*)cnt < G_) __nanosleep(32);
        __threadfence();
    }
    __syncthreads();
}

// ===========================================================================
__global__ void __launch_bounds__(1024, 1) fused_attn(
    const float* __restrict__ x1, const float* __restrict__ x2,
    const float* __restrict__ W1, const float* __restrict__ bb1,
    const float* __restrict__ U1, const float* __restrict__ W2,
    const float* __restrict__ bb2, const float* __restrict__ U2,
    float* __restrict__ out)
{
    const int b    = blockIdx.x >> 2;
    const int g    = blockIdx.x & 3;
    const int tid  = threadIdx.x;
    const int lane = tid & 31;
    const int w    = tid >> 5;
    const int t0   = g * ROWS;
    const int rbase = w * RPW;

    __shared__ float4 sred[2][NW][32];   // warp-reduction scratch (32 KB)
    __shared__ float  vsh[2][E_];        // s (phase B) then c (phase C)
    __shared__ float  tsh[2][ROWS];      // d -> et -> local softmax weights
    __shared__ float  stm[2][16];        // per-warp maxes (16 warps per tensor)
    __shared__ float  stz[2][16];        // per-warp exp sums
    __shared__ float  s_m[2];            // CTA-local max

    const float4* p1 = (const float4*)(x1 + ((size_t)b * T_ + t0) * E_);
    const float4* p2 = (const float4*)(x2 + ((size_t)b * T_ + t0) * E_);

    // ======== Phase A: pure streaming column sums (no shuffles) ============
    {
        float4 s1a = {0,0,0,0}, s2a = {0,0,0,0};
        #pragma unroll 4
        for (int rr = 0; rr < RPW; rr++) {
            int row = rbase + rr;
            float4 v1 = __ldg(p1 + row * 32 + lane);
            float4 v2 = __ldg(p2 + row * 32 + lane);
            s1a.x += v1.x; s1a.y += v1.y; s1a.z += v1.z; s1a.w += v1.w;
            s2a.x += v2.x; s2a.y += v2.y; s2a.z += v2.z; s2a.w += v2.w;
        }
        sred[0][w][lane] = s1a;
        sred[1][w][lane] = s2a;
        __syncthreads();
        if (tid < 64) {
            int ti = tid >> 5;
            float4 s = sred[ti][0][lane];
            #pragma unroll
            for (int k = 1; k < NW; k++) {
                float4 v = sred[ti][k][lane];
                s.x += v.x; s.y += v.y; s.z += v.z; s.w += v.w;
            }
            ((float4*)&g_s_part[ti][b][g][0])[lane] = s;
        }
    }
    batch_bar(&g_bar[b][0]);

    if (tid < 256) {
        int ti = tid >> 7, e = tid & 127;
        float acc = 0.f;
        #pragma unroll
        for (int gg = 0; gg < G_; gg++) acc += g_s_part[ti][b][gg][e];
        vsh[ti][e] = acc;
    }
    __syncthreads();

    // ======== Phase B: c partials + row dots d (merged 4-way butterfly) ====
    {
        float4 s1l = ((const float4*)vsh[0])[lane];
        float4 s2l = ((const float4*)vsh[1])[lane];
        float4 w1l = ((const float4*)W1)[lane];
        float4 w2l = ((const float4*)W2)[lane];
        float4 c1a = {0,0,0,0}, c2a = {0,0,0,0};
        #pragma unroll 2
        for (int rr = 0; rr < RPW; rr++) {
            int row = rbase + rr;
            float4 v1 = __ldg(p1 + row * 32 + lane);
            float4 v2 = __ldg(p2 + row * 32 + lane);
            float q0 = dot4(v1, s2l);   // a1
            float q1 = dot4(v2, s1l);   // a2
            float q2 = dot4(v1, w1l);   // d1
            float q3 = dot4(v2, w2l);   // d2
            q0 += __shfl_xor_sync(0xffffffffu, q0, 16);
            q1 += __shfl_xor_sync(0xffffffffu, q1, 16);
            q2 += __shfl_xor_sync(0xffffffffu, q2, 16);
            q3 += __shfl_xor_sync(0xffffffffu, q3, 16);
            q0 += __shfl_xor_sync(0xffffffffu, q0, 8);
            q1 += __shfl_xor_sync(0xffffffffu, q1, 8);
            q2 += __shfl_xor_sync(0xffffffffu, q2, 8);
            q3 += __shfl_xor_sync(0xffffffffu, q3, 8);
            float q = (lane < 8) ? q0 : (lane < 16) ? q1 : (lane < 24) ? q2 : q3;
            q += __shfl_xor_sync(0xffffffffu, q, 4);
            q += __shfl_xor_sync(0xffffffffu, q, 2);
            q += __shfl_xor_sync(0xffffffffu, q, 1);
            float a1 = __shfl_sync(0xffffffffu, q, 0);
            float a2 = __shfl_sync(0xffffffffu, q, 8);
            if (lane == 16) tsh[0][row] = q;   // d1
            if (lane == 24) tsh[1][row] = q;   // d2
            c1a.x = fmaf(a1, v2.x, c1a.x); c1a.y = fmaf(a1, v2.y, c1a.y);
            c1a.z = fmaf(a1, v2.z, c1a.z); c1a.w = fmaf(a1, v2.w, c1a.w);
            c2a.x = fmaf(a2, v1.x, c2a.x); c2a.y = fmaf(a2, v1.y, c2a.y);
            c2a.z = fmaf(a2, v1.z, c2a.z); c2a.w = fmaf(a2, v1.w, c2a.w);
        }
        sred[0][w][lane] = c1a;
        sred[1][w][lane] = c2a;
        __syncthreads();
        if (tid < 64) {
            int ti = tid >> 5;
            float4 s = sred[ti][0][lane];
            #pragma unroll
            for (int k = 1; k < NW; k++) {
                float4 v = sred[ti][k][lane];
                s.x += v.x; s.y += v.y; s.z += v.z; s.w += v.w;
            }
            ((float4*)&g_c_part[ti][b][g][0])[lane] = s;
        }
    }
    batch_bar(&g_bar[b][1]);

    if (tid < 256) {
        int ti = tid >> 7, e = tid & 127;
        float acc = 0.f;
        #pragma unroll
        for (int gg = 0; gg < G_; gg++) acc += g_c_part[ti][b][gg][e];
        vsh[ti][e] = acc * INV_T;
    }
    __syncthreads();

    // ======== Phase C: logits + CTA-LOCAL softmax (no global barrier) ======
    {
        int p    = tid >> 9;
        int tloc = tid & 511;
        int wp   = tloc >> 5;
        const float* U    = p ? U2  : U1;
        const float* bias = p ? bb2 : bb1;
        int t = t0 + tloc;
        float acc = 0.f;
        #pragma unroll 8
        for (int e = 0; e < E_; e++)
            acc = fmaf(vsh[p][e], __ldg(&U[e * T_ + t]), acc);
        float et = acc + tsh[p][tloc] + __ldg(&bias[t]);   // own slot: no race
        float m = wmax(et);
        if (lane == 0) stm[p][wp] = m;
        __syncthreads();
        if (tid < 2) {                 // CTA-local max per tensor
            float mm = stm[tid][0];
            #pragma unroll
            for (int i = 1; i < 16; i++) mm = fmaxf(mm, stm[tid][i]);
            s_m[tid] = mm;
        }
        __syncthreads();
        float wt = __expf(et - s_m[p]);    // local (unnormalized) weight
        tsh[p][tloc] = wt;
        float z = wsum(wt);
        if (lane == 0) stz[p][wp] = z;
        __syncthreads();
        if (tid < 2) {                 // local Z -> global stats (no barrier)
            float zz = 0.f;
            #pragma unroll
            for (int i = 0; i < 16; i++) zz += stz[tid][i];
            g_stats[tid][b][g] = make_float2(s_m[tid], zz);
        }
        // tsh weights complete for ALL threads after the stz __syncthreads
    }
    __syncthreads();

    // ======== Phase D: weighted sums with LOCAL weights ====================
    {
        float4 o1a = {0,0,0,0}, o2a = {0,0,0,0};
        #pragma unroll 2
        for (int rr = 0; rr < RPW; rr++) {
            int row = rbase + rr;
            float wt1 = tsh[0][row];
            float wt2 = tsh[1][row];
            float4 v1 = __ldg(p1 + row * 32 + lane);
            float4 v2 = __ldg(p2 + row * 32 + lane);
            o1a.x = fmaf(wt1, v1.x, o1a.x); o1a.y = fmaf(wt1, v1.y, o1a.y);
            o1a.z = fmaf(wt1, v1.z, o1a.z); o1a.w = fmaf(wt1, v1.w, o1a.w);
            o2a.x = fmaf(wt2, v2.x, o2a.x); o2a.y = fmaf(wt2, v2.y, o2a.y);
            o2a.z = fmaf(wt2, v2.z, o2a.z); o2a.w = fmaf(wt2, v2.w, o2a.w);
        }
        sred[0][w][lane] = o1a;
        sred[1][w][lane] = o2a;
        __syncthreads();
        if (tid < 64) {
            int ti = tid >> 5;
            float4 s = sred[ti][0][lane];
            #pragma unroll
            for (int k = 1; k < NW; k++) {
                float4 v = sred[ti][k][lane];
                s.x += v.x; s.y += v.y; s.z += v.z; s.w += v.w;
            }
            ((float4*)&g_o_part[ti][b][g][0])[lane] = s;
        }
    }
    batch_bar(&g_bar[b][2]);

    // ======== Output: rescale per-CTA partials by e^{m_g-m}, divide by Z ===
    if (tid < 64) {
        int idx = g * 64 + tid;
        int ti = idx >> 7, e = idx & 127;
        float2 st[G_];
        #pragma unroll
        for (int gg = 0; gg < G_; gg++) st[gg] = g_stats[ti][b][gg];
        float m = st[0].x;
        #pragma unroll
        for (int gg = 1; gg < G_; gg++) m = fmaxf(m, st[gg].x);
        float Z = 0.f, acc = 0.f;
        #pragma unroll
        for (int gg = 0; gg < G_; gg++) {
            float sc = __expf(st[gg].x - m);
            Z   += st[gg].y * sc;
            acc += g_o_part[ti][b][gg][e] * sc;
        }
        out[b * 256 + idx] = acc / Z;
    }

    // ---------------- cleanup: last CTA of the batch resets counters -------
    __syncthreads();
    if (tid == 0) {
        unsigned old = atomicAdd(&g_bar[b][3], 1u);
        if (old == G_ - 1) {
            #pragma unroll
            for (int i = 0; i < 4; i++) g_bar[b][i] = 0u;
        }
    }
}

// ===========================================================================
extern "C" void kernel_launch(void* const* d_in, const int* in_sizes, int n_in,
                              void* d_out, int out_size)
{
    const float* x1 = (const float*)d_in[0];
    const float* x2 = (const float*)d_in[1];
    const float* W1 = (const float*)d_in[2];
    const float* b1 = (const float*)d_in[3];
    const float* U1 = (const float*)d_in[4];
    const float* W2 = (const float*)d_in[5];
    const float* b2 = (const float*)d_in[6];
    const float* U2 = (const float*)d_in[7];
    float* out = (float*)d_out;

    fused_attn<<<B_ * G_, 1024>>>(x1, x2, W1, b1, U1, W2, b2, U2, out);
}

// round 16
// speedup vs baseline: 1.4121x; 1.4121x over previous
#include <cuda_runtime.h>
#include <cstddef>

#define B_   32
#define T_   2048
#define E_   128
#define G_   4              // CTAs per batch
#define ROWS 512            // T_ / G_  rows per CTA
#define NW   32             // warps per CTA
#define RPW  16             // rows per warp
#define INV_T (1.0f / 2048.0f)

// ---------------- scratch (device globals; zero-init; no allocation) -------
__device__ float  g_s_part[2][B_][G_][E_];   // per-CTA column-sum partials
__device__ float  g_c_part[2][B_][G_][E_];   // per-CTA c partials
__device__ float2 g_stats [2][B_][G_];       // per-CTA (max, sumexp) stats
__device__ float  g_o_part[2][B_][G_][E_];   // per-CTA weighted-sum partials
__device__ unsigned g_bar[B_][5];            // per-batch phase counters (self-reset)

static __device__ __forceinline__ float dot4(float4 a, float4 b) {
    return fmaf(a.x, b.x, fmaf(a.y, b.y, fmaf(a.z, b.z, a.w * b.w)));
}
static __device__ __forceinline__ float wsum(float v) {
    #pragma unroll
    for (int off = 16; off; off >>= 1) v += __shfl_xor_sync(0xffffffffu, v, off);
    return v;
}
static __device__ __forceinline__ float wmax(float v) {
    #pragma unroll
    for (int off = 16; off; off >>= 1) v = fmaxf(v, __shfl_xor_sync(0xffffffffu, v, off));
    return v;
}

// batch-scoped barrier: all G_ CTAs of this batch arrive, then proceed.
// All 128 CTAs are co-resident (grid 128 <= 148 SMs, 1 CTA/SM): spin is safe.
static __device__ __forceinline__ void batch_bar(unsigned* cnt) {
    __threadfence();
    __syncthreads();
    if (threadIdx.x == 0) {
        atomicAdd(cnt, 1u);
        while (*(volatile unsigned*)cnt < G_) __nanosleep(32);
        __threadfence();
    }
    __syncthreads();
}

// ===========================================================================
__global__ void __launch_bounds__(1024, 1) fused_attn(
    const float* __restrict__ x1, const float* __restrict__ x2,
    const float* __restrict__ W1, const float* __restrict__ bb1,
    const float* __restrict__ U1, const float* __restrict__ W2,
    const float* __restrict__ bb2, const float* __restrict__ U2,
    float* __restrict__ out)
{
    const int b    = blockIdx.x >> 2;
    const int g    = blockIdx.x & 3;
    const int tid  = threadIdx.x;
    const int lane = tid & 31;
    const int w    = tid >> 5;
    const int t0   = g * ROWS;
    const int rbase = w * RPW;

    __shared__ float4 sred[2][NW][32];   // warp-reduction scratch (32 KB)
    __shared__ float  vsh[2][E_];        // s (phase B) then c (phase C)
    __shared__ float  tsh[2][ROWS];      // d -> et -> softmax weights
    __shared__ float2 stsh[2][16];       // per-warp softmax stats
    __shared__ float  s_m[2], s_iz[2];

    const float4* p1 = (const float4*)(x1 + ((size_t)b * T_ + t0) * E_);
    const float4* p2 = (const float4*)(x2 + ((size_t)b * T_ + t0) * E_);

    // ======== Phase A: streaming column sums, explicit 4-row load batches ==
    // 8 LDG.128 issued back-to-back before any consumption: ~4KB/warp in
    // flight -> covers L2 latency for the L2-hot replay case.
    {
        float4 s1a = {0,0,0,0}, s2a = {0,0,0,0};
        #pragma unroll
        for (int rb = 0; rb < RPW; rb += 4) {
            float4 v1[4], v2[4];
            #pragma unroll
            for (int k = 0; k < 4; k++) {
                v1[k] = __ldg(p1 + (rbase + rb + k) * 32 + lane);
                v2[k] = __ldg(p2 + (rbase + rb + k) * 32 + lane);
            }
            #pragma unroll
            for (int k = 0; k < 4; k++) {
                s1a.x += v1[k].x; s1a.y += v1[k].y; s1a.z += v1[k].z; s1a.w += v1[k].w;
                s2a.x += v2[k].x; s2a.y += v2[k].y; s2a.z += v2[k].z; s2a.w += v2[k].w;
            }
        }
        sred[0][w][lane] = s1a;
        sred[1][w][lane] = s2a;
        __syncthreads();
        if (tid < 64) {
            int ti = tid >> 5;
            float4 s = sred[ti][0][lane];
            #pragma unroll
            for (int k = 1; k < NW; k++) {
                float4 v = sred[ti][k][lane];
                s.x += v.x; s.y += v.y; s.z += v.z; s.w += v.w;
            }
            ((float4*)&g_s_part[ti][b][g][0])[lane] = s;
        }
    }
    batch_bar(&g_bar[b][0]);

    // full column sums into smem
    if (tid < 256) {
        int ti = tid >> 7, e = tid & 127;
        float acc = 0.f;
        #pragma unroll
        for (int gg = 0; gg < G_; gg++) acc += g_s_part[ti][b][gg][e];
        vsh[ti][e] = acc;
    }
    __syncthreads();

    // ======== Phase B: c partials + row dots d (merged 4-way butterfly) ====
    {
        float4 s1l = ((const float4*)vsh[0])[lane];
        float4 s2l = ((const float4*)vsh[1])[lane];
        float4 w1l = ((const float4*)W1)[lane];
        float4 w2l = ((const float4*)W2)[lane];
        float4 c1a = {0,0,0,0}, c2a = {0,0,0,0};
        #pragma unroll 2
        for (int rr = 0; rr < RPW; rr++) {
            int row = rbase + rr;
            float4 v1 = __ldg(p1 + row * 32 + lane);
            float4 v2 = __ldg(p2 + row * 32 + lane);
            float q0 = dot4(v1, s2l);   // a1 = x1 . s2
            float q1 = dot4(v2, s1l);   // a2 = x2 . s1
            float q2 = dot4(v1, w1l);   // d1 = x1 . W1
            float q3 = dot4(v2, w2l);   // d2 = x2 . W2
            q0 += __shfl_xor_sync(0xffffffffu, q0, 16);
            q1 += __shfl_xor_sync(0xffffffffu, q1, 16);
            q2 += __shfl_xor_sync(0xffffffffu, q2, 16);
            q3 += __shfl_xor_sync(0xffffffffu, q3, 16);
            q0 += __shfl_xor_sync(0xffffffffu, q0, 8);
            q1 += __shfl_xor_sync(0xffffffffu, q1, 8);
            q2 += __shfl_xor_sync(0xffffffffu, q2, 8);
            q3 += __shfl_xor_sync(0xffffffffu, q3, 8);
            float q = (lane < 8) ? q0 : (lane < 16) ? q1 : (lane < 24) ? q2 : q3;
            q += __shfl_xor_sync(0xffffffffu, q, 4);
            q += __shfl_xor_sync(0xffffffffu, q, 2);
            q += __shfl_xor_sync(0xffffffffu, q, 1);
            float a1 = __shfl_sync(0xffffffffu, q, 0);
            float a2 = __shfl_sync(0xffffffffu, q, 8);
            if (lane == 16) tsh[0][row] = q;   // d1
            if (lane == 24) tsh[1][row] = q;   // d2
            c1a.x = fmaf(a1, v2.x, c1a.x); c1a.y = fmaf(a1, v2.y, c1a.y);
            c1a.z = fmaf(a1, v2.z, c1a.z); c1a.w = fmaf(a1, v2.w, c1a.w);
            c2a.x = fmaf(a2, v1.x, c2a.x); c2a.y = fmaf(a2, v1.y, c2a.y);
            c2a.z = fmaf(a2, v1.z, c2a.z); c2a.w = fmaf(a2, v1.w, c2a.w);
        }
        sred[0][w][lane] = c1a;
        sred[1][w][lane] = c2a;
        __syncthreads();
        if (tid < 64) {
            int ti = tid >> 5;
            float4 s = sred[ti][0][lane];
            #pragma unroll
            for (int k = 1; k < NW; k++) {
                float4 v = sred[ti][k][lane];
                s.x += v.x; s.y += v.y; s.z += v.z; s.w += v.w;
            }
            ((float4*)&g_c_part[ti][b][g][0])[lane] = s;
        }
    }
    batch_bar(&g_bar[b][1]);

    // full c (scaled) into smem
    if (tid < 256) {
        int ti = tid >> 7, e = tid & 127;
        float acc = 0.f;
        #pragma unroll
        for (int gg = 0; gg < G_; gg++) acc += g_c_part[ti][b][gg][e];
        vsh[ti][e] = acc * INV_T;
    }
    __syncthreads();

    // ======== Phase C: logits + per-CTA softmax stats ======================
    {
        int p    = tid >> 9;
        int tloc = tid & 511;
        int wp   = tloc >> 5;              // warp index within tensor (0..15)
        const float* U    = p ? U2  : U1;
        const float* bias = p ? bb2 : bb1;
        int t = t0 + tloc;
        float acc = 0.f;
        #pragma unroll 8
        for (int e = 0; e < E_; e++)
            acc = fmaf(vsh[p][e], __ldg(&U[e * T_ + t]), acc);
        float et = acc + tsh[p][tloc] + __ldg(&bias[t]);
        __syncthreads();                   // tsh read (d) before overwrite
        tsh[p][tloc] = et;
        float m = wmax(et);
        float z = wsum(__expf(et - m));
        if (lane == 0) stsh[p][wp] = make_float2(m, z);
    }
    __syncthreads();
    if (tid < 2) {
        float m = -3.4e38f;
        #pragma unroll
        for (int i = 0; i < 16; i++) m = fmaxf(m, stsh[tid][i].x);
        float z = 0.f;
        #pragma unroll
        for (int i = 0; i < 16; i++) {
            float2 st = stsh[tid][i];
            z += st.y * __expf(st.x - m);
        }
        g_stats[tid][b][g] = make_float2(m, z);
    }
    batch_bar(&g_bar[b][2]);
    if (tid < 2) {
        float m = -3.4e38f;
        #pragma unroll
        for (int gg = 0; gg < G_; gg++) m = fmaxf(m, g_stats[tid][b][gg].x);
        float z = 0.f;
        #pragma unroll
        for (int gg = 0; gg < G_; gg++) {
            float2 st = g_stats[tid][b][gg];
            z += st.y * __expf(st.x - m);
        }
        s_m[tid]  = m;
        s_iz[tid] = 1.0f / z;
    }
    __syncthreads();

    // ======== Phase D: softmax weights + weighted sums, 4-row batches ======
    {
        int ti = tid >> 9, rr = tid & 511;     // 1024 threads = 2*ROWS exactly
        tsh[ti][rr] = __expf(tsh[ti][rr] - s_m[ti]) * s_iz[ti];
    }
    __syncthreads();
    {
        float4 o1a = {0,0,0,0}, o2a = {0,0,0,0};
        #pragma unroll
        for (int rb = 0; rb < RPW; rb += 4) {
            float4 v1[4], v2[4];
            #pragma unroll
            for (int k = 0; k < 4; k++) {
                v1[k] = __ldg(p1 + (rbase + rb + k) * 32 + lane);
                v2[k] = __ldg(p2 + (rbase + rb + k) * 32 + lane);
            }
            #pragma unroll
            for (int k = 0; k < 4; k++) {
                int row = rbase + rb + k;
                float wt1 = tsh[0][row];
                float wt2 = tsh[1][row];
                o1a.x = fmaf(wt1, v1[k].x, o1a.x); o1a.y = fmaf(wt1, v1[k].y, o1a.y);
                o1a.z = fmaf(wt1, v1[k].z, o1a.z); o1a.w = fmaf(wt1, v1[k].w, o1a.w);
                o2a.x = fmaf(wt2, v2[k].x, o2a.x); o2a.y = fmaf(wt2, v2[k].y, o2a.y);
                o2a.z = fmaf(wt2, v2[k].z, o2a.z); o2a.w = fmaf(wt2, v2[k].w, o2a.w);
            }
        }
        sred[0][w][lane] = o1a;
        sred[1][w][lane] = o2a;
        __syncthreads();
        if (tid < 64) {
            int ti = tid >> 5;
            float4 s = sred[ti][0][lane];
            #pragma unroll
            for (int k = 1; k < NW; k++) {
                float4 v = sred[ti][k][lane];
                s.x += v.x; s.y += v.y; s.z += v.z; s.w += v.w;
            }
            ((float4*)&g_o_part[ti][b][g][0])[lane] = s;
        }
    }
    batch_bar(&g_bar[b][3]);

    // ---------------- output: CTA g writes its 64 of 256 values ------------
    if (tid < 64) {
        int idx = g * 64 + tid;
        int ti = idx >> 7, e = idx & 127;
        float acc = 0.f;
        #pragma unroll
        for (int gg = 0; gg < G_; gg++) acc += g_o_part[ti][b][gg][e];
        out[b * 256 + idx] = acc;
    }

    // ---------------- cleanup: last CTA of the batch resets counters -------
    __syncthreads();
    if (tid == 0) {
        unsigned old = atomicAdd(&g_bar[b][4], 1u);
        if (old == G_ - 1) {
            #pragma unroll
            for (int i = 0; i < 5; i++) g_bar[b][i] = 0u;
        }
    }
}

// ===========================================================================
extern "C" void kernel_launch(void* const* d_in, const int* in_sizes, int n_in,
                              void* d_out, int out_size)
{
    const float* x1 = (const float*)d_in[0];
    const float* x2 = (const float*)d_in[1];
    const float* W1 = (const float*)d_in[2];
    const float* b1 = (const float*)d_in[3];
    const float* U1 = (const float*)d_in[4];
    const float* W2 = (const float*)d_in[5];
    const float* b2 = (const float*)d_in[6];
    const float* U2 = (const float*)d_in[7];
    float* out = (float*)d_out;

    fused_attn<<<B_ * G_, 1024>>>(x1, x2, W1, b1, U1, W2, b2, U2, out);
}